// round 8
// baseline (speedup 1.0000x reference)
#include <cuda_runtime.h>
#include <cuda_fp16.h>
#include <stdint.h>

#define B_    32
#define C_IN  128
#define H_    64
#define W_    64
#define K_    8
#define C_OUT 128
#define HID   512
#define HW    4096
#define NUNITS 1024         // unit = 2 rows (128 px)
#define GRID_P 296
#define NSTG  36            // 9 taps x 4 ci32-blocks

__device__ float g_pooled[B_ * C_IN];
__device__ float g_alphas[B_ * K_];
__device__ float g_aggb[B_ * C_OUT];
__device__ int   g_ctr;
// x: [b][cb(8)][pixel(4096)][ci16] fp16 (1,048,576 B per b; 131,072 per cb)
__device__ __half g_xt[(size_t)B_ * HW * C_IN];
// w: [b][tap(9)][cb(8)][oc(128)][ci16] fp16 (294,912 B per b; 4096 B per (tap,cb))
__device__ __half g_aw[(size_t)B_ * 9 * C_OUT * C_IN];

__device__ __forceinline__ uint32_t smem_u32(const void* p) {
    uint32_t a;
    asm("{ .reg .u64 t; cvta.to.shared.u64 t, %1; cvt.u32.u64 %0, t; }" : "=r"(a) : "l"(p));
    return a;
}
#define CPA(dst, src, sz) \
    asm volatile("cp.async.cg.shared.global [%0], [%1], 16, %2;" :: "r"(dst), "l"(src), "r"(sz) : "memory")
#define CP_COMMIT() asm volatile("cp.async.commit_group;" ::: "memory")
#define CP_WAIT2()  asm volatile("cp.async.wait_group 2;" ::: "memory")
#define LDSM4(r, a) \
    asm volatile("ldmatrix.sync.aligned.m8n8.x4.shared.b16 {%0,%1,%2,%3}, [%4];" \
        : "=r"((r)[0]), "=r"((r)[1]), "=r"((r)[2]), "=r"((r)[3]) : "r"(a))
#define LDSM2(r, a) \
    asm volatile("ldmatrix.sync.aligned.m8n8.x2.shared.b16 {%0,%1}, [%2];" \
        : "=r"((r)[0]), "=r"((r)[1]) : "r"(a))
#define MMA(c, a, bb) \
    asm volatile("mma.sync.aligned.m16n8k16.row.col.f32.f16.f16.f32 " \
        "{%0,%1,%2,%3}, {%4,%5,%6,%7}, {%8,%9}, {%0,%1,%2,%3};" \
        : "+f"((c)[0]), "+f"((c)[1]), "+f"((c)[2]), "+f"((c)[3]) \
        : "r"((a)[0]), "r"((a)[1]), "r"((a)[2]), "r"((a)[3]), "r"((bb)[0]), "r"((bb)[1]))

// ---------- 1) pool ----------
__global__ __launch_bounds__(256) void pool_kernel(const float* __restrict__ x, float* __restrict__ pooled) {
    int bc = blockIdx.x;
    const float* p = x + (size_t)bc * HW;
    float s = 0.f;
    for (int i = threadIdx.x; i < HW; i += 256) s += p[i];
#pragma unroll
    for (int o = 16; o; o >>= 1) s += __shfl_xor_sync(~0u, s, o);
    __shared__ float red[8];
    if ((threadIdx.x & 31) == 0) red[threadIdx.x >> 5] = s;
    __syncthreads();
    if (threadIdx.x < 8) {
        s = red[threadIdx.x];
#pragma unroll
        for (int o = 4; o; o >>= 1) s += __shfl_xor_sync(0xffu, s, o);
        if (threadIdx.x == 0) pooled[bc] = s * (1.f / (float)HW);
    }
}

// ---------- 2) attention ----------
__global__ __launch_bounds__(512) void attn_kernel(const float* __restrict__ pooled, const float* __restrict__ prompt,
        const float* __restrict__ w1, const float* __restrict__ b1, const float* __restrict__ w2,
        const float* __restrict__ b2, const float* __restrict__ kbias,
        float* __restrict__ alphas, float* __restrict__ aggb) {
    int b = blockIdx.x, t = threadIdx.x;
    __shared__ float sp[C_IN], sh[HID], ss[HID], sc[K_], sal[K_];
    if (t < C_IN) sp[t] = pooled[b * C_IN + t];
    __syncthreads();
    { const float* wr = w1 + (size_t)t * C_IN; float a = b1[t];
#pragma unroll 8
      for (int i = 0; i < C_IN; i++) a = fmaf(sp[i], wr[i], a);
      sh[t] = fmaxf(a, 0.f); }
    __syncthreads();
    { const float* wr = w2 + (size_t)t * HID; float a = b2[t];
#pragma unroll 8
      for (int i = 0; i < HID; i++) a = fmaf(sh[i], wr[i], a);
      ss[t] = a; }
    __syncthreads();
    int wr = t >> 5, ln = t & 31;
    if (wr < K_) {
        const float* pr = prompt + (size_t)wr * HID;
        float a = 0.f;
        for (int i = ln; i < HID; i += 32) a = fmaf(ss[i], pr[i], a);
#pragma unroll
        for (int o = 16; o; o >>= 1) a += __shfl_xor_sync(~0u, a, o);
        if (ln == 0) sc[wr] = a;
    }
    __syncthreads();
    if (t == 0) {
        float m = sc[0];
#pragma unroll
        for (int k = 1; k < K_; k++) m = fmaxf(m, sc[k]);
        float e[K_], su = 0.f;
#pragma unroll
        for (int k = 0; k < K_; k++) { e[k] = __expf(sc[k] - m); su += e[k]; }
        float inv = 1.f / su;
#pragma unroll
        for (int k = 0; k < K_; k++) { sal[k] = e[k] * inv; alphas[b * K_ + k] = sal[k]; }
    }
    __syncthreads();
    if (t < C_OUT) {
        float a = 0.f;
#pragma unroll
        for (int k = 0; k < K_; k++) a = fmaf(sal[k], kbias[k * C_OUT + t], a);
        aggb[b * C_OUT + t] = a;
    }
}

// ---------- 3) weight agg -> [b][tap][cb][oc][ci16] fp16 ----------
__global__ __launch_bounds__(128) void aggw_f16_kernel(const float* __restrict__ kw, const float* __restrict__ alphas,
        __half* __restrict__ A) {
    int oc = blockIdx.x, b = blockIdx.y, ci = threadIdx.x;
    __shared__ float skw[K_][C_IN * 9];
    __shared__ float a[K_];
    if (ci < K_) a[ci] = alphas[b * K_ + ci];
    for (int k = 0; k < K_; k++)
        for (int i = ci; i < C_IN * 9; i += 128)
            skw[k][i] = kw[(size_t)(k * C_OUT + oc) * (C_IN * 9) + i];
    __syncthreads();
    float acc[9];
#pragma unroll
    for (int t = 0; t < 9; t++) acc[t] = 0.f;
#pragma unroll
    for (int k = 0; k < K_; k++) {
        float al = a[k];
        const float* p = &skw[k][ci * 9];
#pragma unroll
        for (int t = 0; t < 9; t++) acc[t] = fmaf(al, p[t], acc[t]);
    }
#pragma unroll
    for (int t = 0; t < 9; t++) {
        size_t o = ((((size_t)(b * 9 + t) * 8 + (ci >> 4)) * C_OUT) + oc) * 16 + (ci & 15);
        A[o] = __float2half_rn(acc[t]);
    }
}

// ---------- 4) x -> [b][cb][p][ci16] fp16 ----------
__global__ __launch_bounds__(256) void xt_f16_kernel(const float* __restrict__ x, __half* __restrict__ X) {
    __shared__ float t[32][33];
    int b = blockIdx.z, p0 = blockIdx.x * 32, c0 = blockIdx.y * 32;
    int tx = threadIdx.x, ty = threadIdx.y;
    int tid = ty * 32 + tx;
#pragma unroll
    for (int i = 0; i < 4; i++)
        t[ty + 8 * i][tx] = x[((size_t)b * C_IN + c0 + ty + 8 * i) * HW + p0 + tx];
    __syncthreads();
#pragma unroll
    for (int i = 0; i < 2; i++) {
        int idx = tid + 256 * i;
        int sub  = idx & 7;
        int pxcb = idx >> 3;
        int pxl  = pxcb & 31;
        int cbl  = pxcb >> 5;
        int cl   = cbl * 16 + sub * 2;
        int c    = c0 + cl;
        __half2 v = __floats2half2_rn(t[cl][pxl], t[cl + 1][pxl]);
        size_t o = ((((size_t)b * 8 + (c >> 4)) * HW + p0 + pxl) * 16 + (c & 15)) >> 1;
        ((__half2*)X)[o] = v;
    }
}

// ---------- counter reset ----------
__global__ void reset_ctr_kernel() { g_ctr = 0; }

// ---------- 5) persistent HMMA conv: fp16 1-pass, k32 stages ----------
#define PITCH 80
#define SM_A  0
#define SM_B  10240
#define BUF_SZ 20480
__global__ __launch_bounds__(256, 2) void conv_mma_kernel(
        const __half* __restrict__ aw, const __half* __restrict__ xt,
        const float* __restrict__ aggb, float* __restrict__ out)
{
    extern __shared__ __align__(128) char sm[];
    const uint32_t sbase = smem_u32(sm);
    __shared__ int s_nu[2];
    const int tid = threadIdx.x, wid = tid >> 5, lane = tid & 31;
    const int warp_m = wid & 3, warp_n = wid >> 2;

    // staging: thread handles one oc row (A) and one px row (B), 32B each (half of 64B row)
    const int arow = tid >> 1, asel = tid & 1;     // asel: which ci16 sub-block
    const uint32_t aDst = sbase + SM_A + arow * PITCH + asel * 32;
    const uint32_t bDst = sbase + SM_B + arow * PITCH + asel * 32;
    const uint32_t offA = (uint32_t)((warp_m * 32 + (lane & 15)) * PITCH + (lane >> 4) * 16);
    const uint32_t offB = (uint32_t)((warp_n * 64 + (lane & 7)) * PITCH + ((lane >> 3) & 1) * 16);

    if (tid == 0) s_nu[0] = atomicAdd(&g_ctr, 1);
    __syncthreads();
    int c_u = s_nu[0];
    if (tid == 0) s_nu[1] = atomicAdd(&g_ctr, 1);
    int nslot = 1;

    int l_u = c_u, l_s = 0, l_buf = 0;

    float C[8][2][4];
#pragma unroll
    for (int i = 0; i < 8; i++)
#pragma unroll
        for (int j = 0; j < 2; j++)
#pragma unroll
            for (int q = 0; q < 4; q++) C[i][j][q] = 0.f;

#define ISSUE() do { \
    if (l_u < NUNITS) { \
        int b_ = l_u >> 5, y0_ = (l_u & 31) * 2; \
        int tap_ = l_s >> 2, j_ = l_s & 3; \
        int cb_ = 2 * j_ + asel; \
        int yy_ = y0_ + (arow >> 6) + tap_ / 3 - 1; \
        int xx_ = (arow & 63) + tap_ % 3 - 1; \
        bool v_ = ((unsigned)yy_ < 64u) && ((unsigned)xx_ < 64u); \
        size_t boff_ = (size_t)b_ * 1048576 + (size_t)cb_ * 131072 \
                     + (v_ ? (size_t)(yy_ * 64 + xx_) * 32 : 0); \
        unsigned bsz_ = v_ ? 16u : 0u; \
        uint32_t bs_ = l_buf * BUF_SZ; \
        const char* as_ = (const char*)aw + (size_t)b_ * 294912 + (size_t)(tap_ * 8 + cb_) * 4096 + arow * 32; \
        CPA(aDst + bs_,      as_,      16u); \
        CPA(aDst + bs_ + 16, as_ + 16, 16u); \
        CPA(bDst + bs_,      (const char*)xt + boff_,      bsz_); \
        CPA(bDst + bs_ + 16, (const char*)xt + boff_ + 16, bsz_); \
    } \
    l_s++; l_buf = (l_buf + 1) & 3; \
} while (0)

    ISSUE(); CP_COMMIT();
    ISSUE(); CP_COMMIT();
    ISSUE(); CP_COMMIT();

    int c_buf = 0;
    while (c_u < NUNITS) {
        for (int c_s = 0; c_s < NSTG; c_s++) {
            CP_WAIT2();
            __syncthreads();
            if (l_s == NSTG) { l_u = s_nu[nslot]; l_s = 0; }
            ISSUE();
            CP_COMMIT();

            const uint32_t bb = sbase + c_buf * BUF_SZ;
            c_buf = (c_buf + 1) & 3;
#pragma unroll
            for (int s = 0; s < 2; s++) {
                uint32_t Af[2][4];
                LDSM4(Af[0], bb + SM_A + offA + s * 32);
                LDSM4(Af[1], bb + SM_A + offA + 16 * PITCH + s * 32);
#pragma unroll
                for (int nt = 0; nt < 8; nt++) {
                    uint32_t Bf[2];
                    LDSM2(Bf, bb + SM_B + offB + nt * 8 * PITCH + s * 32);
                    MMA(C[nt][0], Af[0], Bf);
                    MMA(C[nt][1], Af[1], Bf);
                }
            }
        }

        // epilogue for unit c_u
        {
            int b_ = c_u >> 5, y_ = (c_u & 31) * 2 + warp_n;
            float* orow = out + (size_t)b_ * 128 * HW + y_ * 64;
#pragma unroll
            for (int mt = 0; mt < 2; mt++) {
                int oc0 = warp_m * 32 + mt * 16 + (lane >> 2);
                float bi0 = aggb[b_ * 128 + oc0];
                float bi1 = aggb[b_ * 128 + oc0 + 8];
#pragma unroll
                for (int nt = 0; nt < 8; nt++) {
                    int xcol = nt * 8 + 2 * (lane & 3);
                    float2 w0 = { C[nt][mt][0] + bi0, C[nt][mt][1] + bi0 };
                    float2 w1 = { C[nt][mt][2] + bi1, C[nt][mt][3] + bi1 };
                    *(float2*)(orow + (size_t)oc0 * HW + xcol) = w0;
                    *(float2*)(orow + (size_t)(oc0 + 8) * HW + xcol) = w1;
                }
            }
        }
#pragma unroll
        for (int i = 0; i < 8; i++)
#pragma unroll
            for (int j = 0; j < 2; j++)
#pragma unroll
                for (int q = 0; q < 4; q++) C[i][j][q] = 0.f;

        c_u = s_nu[nslot];
        nslot ^= 1;
        if (tid == 0) s_nu[nslot] = atomicAdd(&g_ctr, 1);
        // s_nu[nslot] next read is >= NSTG-3 syncthreads away -> visible
    }
}

// ---------- host ----------
extern "C" void kernel_launch(void* const* d_in, const int* in_sizes, int n_in,
                              void* d_out, int out_size) {
    const float* x      = (const float*)d_in[0];
    const float* prompt = (const float*)d_in[1];
    const float* w1     = (const float*)d_in[2];
    const float* b1     = (const float*)d_in[3];
    const float* w2     = (const float*)d_in[4];
    const float* b2     = (const float*)d_in[5];
    const float* kw     = (const float*)d_in[6];
    const float* kbias  = (const float*)d_in[7];
    float* out = (float*)d_out;

    float *pooled, *alphas, *aggb;
    __half *xh, *awp;
    cudaGetSymbolAddress((void**)&pooled, g_pooled);
    cudaGetSymbolAddress((void**)&alphas, g_alphas);
    cudaGetSymbolAddress((void**)&aggb,   g_aggb);
    cudaGetSymbolAddress((void**)&xh,     g_xt);
    cudaGetSymbolAddress((void**)&awp,    g_aw);

    cudaFuncSetAttribute(conv_mma_kernel, cudaFuncAttributeMaxDynamicSharedMemorySize, 4 * BUF_SZ);

    pool_kernel<<<B_ * C_IN, 256>>>(x, pooled);
    attn_kernel<<<B_, 512>>>(pooled, prompt, w1, b1, w2, b2, kbias, alphas, aggb);
    aggw_f16_kernel<<<dim3(C_OUT, B_), 128>>>(kw, alphas, awp);
    xt_f16_kernel<<<dim3(HW / 32, C_IN / 32, B_), dim3(32, 8)>>>(x, xh);
    reset_ctr_kernel<<<1, 1>>>();
    conv_mma_kernel<<<GRID_P, 256, 4 * BUF_SZ>>>(awp, xh, aggb, out);
}